// round 8
// baseline (speedup 1.0000x reference)
#include <cuda_runtime.h>
#include <cstdint>

// AtteMatchLay via mma.sync TF32, fully decoupled per-warp cp.async pipelines.
//   dot = (r*m) @ w2^T, n1^2 = (r*r) @ w2^T, n2^2 = (m*m) @ w2^T
//   cos = dot / (max(sqrt(n1^2),eps) * max(sqrt(n2^2),eps))
// 256 CTAs x 32 rows, 8 warps = 2 row-strips x 4 K-quarters.
// Each warp privately stages its own [16 rows][16 k] r,m tiles (5 stages,
// per-warp cp.async groups -> NO mainloop __syncthreads). B = w^2 loaded
// per-thread from W (L1-hot), squared + cvt.rna.tf32 in registers; lanes with
// n >= 20 are zero (cols 20..23 discarded in epilogue). Single kernel launch.

static constexpr int D        = 768;
static constexpr int P        = 20;
static constexpr int ROWS_CTA = 32;
static constexpr int THREADS  = 256;
static constexpr int NROWS    = 8192;
static constexpr int NCTA     = NROWS / ROWS_CTA;   // 256
static constexpr int KCH      = 64;
static constexpr int NCHUNK   = D / KCH;            // 12
static constexpr int STAGES   = 5;

static constexpr int TROW     = 20;                  // padded floats per tile row (16+4)
static constexpr int ARR_B    = 16 * TROW * 4;       // 1280 B per array (r or m)
static constexpr int WARP_STG = 2 * ARR_B;           // 2560 B per warp per stage
static constexpr int STG_B    = 8 * WARP_STG;        // 20480 B per stage
static constexpr int SMEM_TOTAL = STAGES * STG_B;    // 102400 -> 2 CTAs/SM

// epilogue aliases (after mainloop + syncthreads)
static constexpr int OFF_RED = 0;       // 2*3*36*32*4 = 27648 B
static constexpr int OFF_OUT = 28672;   // 32*20*4 = 2560 B

__device__ __forceinline__ uint32_t f2tf32(float x) {
    uint32_t t;
    asm("cvt.rna.tf32.f32 %0, %1;" : "=r"(t) : "f"(x));
    return t;
}
__device__ __forceinline__ uint32_t smem_u32(const void* p) {
    uint32_t a;
    asm("{ .reg .u64 t; cvta.to.shared.u64 t, %1; cvt.u32.u64 %0, t; }" : "=r"(a) : "l"(p));
    return a;
}
__device__ __forceinline__ void cp16(uint32_t dst, const void* src) {
    asm volatile("cp.async.cg.shared.global [%0], [%1], 16;" :: "r"(dst), "l"(src));
}
__device__ __forceinline__ void cp_commit() {
    asm volatile("cp.async.commit_group;" ::: "memory");
}
template <int N>
__device__ __forceinline__ void cp_wait() {
    asm volatile("cp.async.wait_group %0;" :: "n"(N) : "memory");
}
__device__ __forceinline__ void mma8(float* d, const uint32_t* a, uint32_t b0, uint32_t b1) {
    asm volatile(
        "mma.sync.aligned.m16n8k8.row.col.f32.tf32.tf32.f32 "
        "{%0,%1,%2,%3}, {%4,%5,%6,%7}, {%8,%9}, {%0,%1,%2,%3};"
        : "+f"(d[0]), "+f"(d[1]), "+f"(d[2]), "+f"(d[3])
        : "r"(a[0]), "r"(a[1]), "r"(a[2]), "r"(a[3]), "r"(b0), "r"(b1));
}

__global__ void __launch_bounds__(THREADS, 2)
amatch_mma(const float* __restrict__ R, const float* __restrict__ Mx,
           const float* __restrict__ W, float* __restrict__ out)
{
    extern __shared__ char smem[];
    const uint32_t sb = smem_u32(smem);

    const int tid   = threadIdx.x;
    const int lane  = tid & 31;
    const int wid   = tid >> 5;
    const int g     = lane >> 2;
    const int t     = lane & 3;
    const int strip = wid >> 2;
    const int kq    = wid & 3;
    const int row0  = blockIdx.x * ROWS_CTA;

    // per-warp staging: 64 float4 per array; this thread covers f = lane, lane+32
    // f -> tile row f>>2, k4 = f&3 (16 B)
    const uint32_t wbase = sb + (uint32_t)wid * WARP_STG;
    const size_t grow = (size_t)(row0 + strip * 16) * D + kq * 16;   // + row*D + c*64 + k4*4

    auto issue_stage = [&](int c, int s) {
        const uint32_t stg = wbase + (uint32_t)s * STG_B;
#pragma unroll
        for (int h = 0; h < 2; h++) {
            const int f   = lane + h * 32;
            const int row = f >> 2;
            const int k4  = f & 3;
            const size_t go = grow + (size_t)row * D + (size_t)c * KCH + k4 * 4;
            const uint32_t so = (uint32_t)(row * (TROW * 4) + k4 * 16);
            cp16(stg + so,         R  + go);
            cp16(stg + ARR_B + so, Mx + go);
        }
        cp_commit();
    };

    // per-thread B pointers (n = nt*8 + g); n >= P lanes read zero
    const float* wp[3];
    bool wv[3];
#pragma unroll
    for (int nt = 0; nt < 3; nt++) {
        const int n = nt * 8 + g;
        wv[nt] = (n < P);
        wp[nt] = W + (size_t)(wv[nt] ? n : 0) * D;
    }

    float acc[3][3][4];
#pragma unroll
    for (int a = 0; a < 3; a++)
#pragma unroll
        for (int b = 0; b < 3; b++)
#pragma unroll
            for (int j = 0; j < 4; j++) acc[a][b][j] = 0.f;

    // prologue: stages 0..3 (prefetch lead 4; stage c+4 reuses the slot freed at c-1)
#pragma unroll
    for (int s = 0; s < STAGES - 1; s++) issue_stage(s, s);

    int sidx = 0;   // c % STAGES
    for (int c = 0; c < NCHUNK; ++c) {
        // chunk c's group complete when pending <= min(3, 11 - c)
        if (c <= NCHUNK - 4)      cp_wait<3>();
        else if (c == NCHUNK - 3) cp_wait<2>();
        else if (c == NCHUNK - 2) cp_wait<1>();
        else                      cp_wait<0>();

        if (c + STAGES - 1 < NCHUNK) {
            int s2 = sidx + STAGES - 1;
            if (s2 >= STAGES) s2 -= STAGES;
            issue_stage(c + STAGES - 1, s2);
        }

        const float* sr = reinterpret_cast<const float*>(smem + sidx * STG_B + wid * WARP_STG);
        const float* sm = sr + 16 * TROW;

#pragma unroll
        for (int it = 0; it < 2; it++) {
            const int kl  = it * 8 + t;              // k within this warp's 16-K slice
            const int kgl = c * KCH + kq * 16 + kl;  // global k (for W)

            const int i0 = g * TROW + kl;
            const int i1 = i0 + 8 * TROW;
            const float r0 = sr[i0], r1 = sr[i1], r2 = sr[i0 + 4], r3 = sr[i1 + 4];
            const float m0 = sm[i0], m1 = sm[i1], m2 = sm[i0 + 4], m3 = sm[i1 + 4];

            uint32_t arm[4] = { f2tf32(r0 * m0), f2tf32(r1 * m1), f2tf32(r2 * m2), f2tf32(r3 * m3) };
            uint32_t arr[4] = { f2tf32(r0 * r0), f2tf32(r1 * r1), f2tf32(r2 * r2), f2tf32(r3 * r3) };
            uint32_t amm[4] = { f2tf32(m0 * m0), f2tf32(m1 * m1), f2tf32(m2 * m2), f2tf32(m3 * m3) };

#pragma unroll
            for (int nt = 0; nt < 3; nt++) {
                const float w0 = wv[nt] ? __ldg(wp[nt] + kgl)     : 0.f;
                const float w1 = wv[nt] ? __ldg(wp[nt] + kgl + 4) : 0.f;
                const uint32_t b0 = f2tf32(w0 * w0);
                const uint32_t b1 = f2tf32(w1 * w1);
                mma8(acc[0][nt], arm, b0, b1);
                mma8(acc[1][nt], arr, b0, b1);
                mma8(acc[2][nt], amm, b0, b1);
            }
        }

        if (++sidx == STAGES) sidx = 0;
    }
    __syncthreads();   // all warps done with stage buffers before aliasing

    // ---- reduce over the 4 K-quarter warps per strip ----
    float* s_red = reinterpret_cast<float*>(smem + OFF_RED);
    if (kq > 0) {
        float* dst = s_red + (size_t)(strip * 3 + (kq - 1)) * 36 * 32 + lane;
#pragma unroll
        for (int a = 0; a < 3; a++)
#pragma unroll
            for (int b = 0; b < 3; b++)
#pragma unroll
                for (int j = 0; j < 4; j++)
                    dst[((a * 3 + b) * 4 + j) * 32] = acc[a][b][j];
    }
    __syncthreads();

    float* s_out = reinterpret_cast<float*>(smem + OFF_OUT);
    if (kq == 0) {
#pragma unroll
        for (int s2 = 0; s2 < 3; s2++) {
            const float* src = s_red + (size_t)(strip * 3 + s2) * 36 * 32 + lane;
#pragma unroll
            for (int a = 0; a < 3; a++)
#pragma unroll
                for (int b = 0; b < 3; b++)
#pragma unroll
                    for (int j = 0; j < 4; j++)
                        acc[a][b][j] += src[((a * 3 + b) * 4 + j) * 32];
        }
        const float EPS = 1e-8f;
#pragma unroll
        for (int nt = 0; nt < 3; nt++) {
#pragma unroll
            for (int j = 0; j < 4; j++) {
                const int col = nt * 8 + 2 * t + (j & 1);
                const int row = strip * 16 + g + (j >> 1) * 8;
                if (col < P) {
                    const float dot = acc[0][nt][j];
                    const float a2  = acc[1][nt][j];
                    const float b2  = acc[2][nt][j];
                    s_out[row * P + col] =
                        dot / (fmaxf(sqrtf(a2), EPS) * fmaxf(sqrtf(b2), EPS));
                }
            }
        }
    }
    __syncthreads();

    if (tid < ROWS_CTA * P / 4) {
        float4 v = *reinterpret_cast<float4*>(s_out + tid * 4);
        *reinterpret_cast<float4*>(out + (size_t)row0 * P + tid * 4) = v;
    }
}

extern "C" void kernel_launch(void* const* d_in, const int* in_sizes, int n_in,
                              void* d_out, int out_size)
{
    const float* repres  = (const float*)d_in[0];
    const float* max_att = (const float*)d_in[1];
    const float* weight  = (const float*)d_in[2];
    float* out = (float*)d_out;

    cudaFuncSetAttribute(amatch_mma,
                         cudaFuncAttributeMaxDynamicSharedMemorySize, SMEM_TOTAL);

    amatch_mma<<<NCTA, THREADS, SMEM_TOTAL>>>(repres, max_att, weight, out);
}

// round 9
// speedup vs baseline: 1.0343x; 1.0343x over previous
#include <cuda_runtime.h>
#include <cstdint>

// AtteMatchLay via mma.sync TF32 + cp.async, small-CTA high-occupancy version.
//   dot = (r*m) @ w2^T, n1^2 = (r*r) @ w2^T, n2^2 = (m*m) @ w2^T
//   cos = dot / (max(sqrt(n1^2),eps) * max(sqrt(n2^2),eps))
// 512 CTAs x 16 rows, 128 threads = 4 warps = 4 K-quarters of one 16-row strip.
// Per chunk (64 K): cp.async stages r, m ([16][68]) and raw W slice ([24][68],
// rows 20..23 zero-filled); w^2 + cvt.rna.tf32 computed at fragment read.
// 3 stages x 15232 B = 45696 B smem -> 5 CTAs/SM (reg-feasible at 128 thr).
// Single kernel launch (no w2 prep kernel).

static constexpr int D        = 768;
static constexpr int P        = 20;
static constexpr int NPAD     = 24;
static constexpr int ROWS_CTA = 16;
static constexpr int THREADS  = 128;
static constexpr int NROWS    = 8192;
static constexpr int NCTA     = NROWS / ROWS_CTA;   // 512
static constexpr int KCH      = 64;
static constexpr int NCHUNK   = D / KCH;            // 12
static constexpr int STAGES   = 3;

static constexpr int SA = 68;                        // row stride (floats), conflict-free
static constexpr int A_ARR   = ROWS_CTA * SA * 4;    // 4352 B per array (r or m)
static constexpr int B_ARR   = NPAD * SA * 4;        // 6528 B (W slice, [n][k] layout)
static constexpr int STG_B   = 2 * A_ARR + B_ARR;    // 15232 B
static constexpr int SMEM_TOTAL = STAGES * STG_B;    // 45696 B -> 5 CTAs/SM

// epilogue aliases (after mainloop + syncthreads)
static constexpr int OFF_RED = 0;       // 3*36*32*4 = 13824 B
static constexpr int OFF_OUT = 13824;   // 16*20*4 = 1280 B

__device__ __forceinline__ uint32_t f2tf32(float x) {
    uint32_t t;
    asm("cvt.rna.tf32.f32 %0, %1;" : "=r"(t) : "f"(x));
    return t;
}
__device__ __forceinline__ uint32_t smem_u32(const void* p) {
    uint32_t a;
    asm("{ .reg .u64 t; cvta.to.shared.u64 t, %1; cvt.u32.u64 %0, t; }" : "=r"(a) : "l"(p));
    return a;
}
__device__ __forceinline__ void cp16(uint32_t dst, const void* src) {
    asm volatile("cp.async.cg.shared.global [%0], [%1], 16;" :: "r"(dst), "l"(src));
}
// predicated source: valid=0 -> zero-fill 16 bytes (no global read)
__device__ __forceinline__ void cp16p(uint32_t dst, const void* src, int srcbytes) {
    asm volatile("cp.async.cg.shared.global [%0], [%1], 16, %2;"
                 :: "r"(dst), "l"(src), "r"(srcbytes));
}
__device__ __forceinline__ void cp_commit() {
    asm volatile("cp.async.commit_group;" ::: "memory");
}
template <int N>
__device__ __forceinline__ void cp_wait() {
    asm volatile("cp.async.wait_group %0;" :: "n"(N) : "memory");
}
__device__ __forceinline__ void mma8(float* d, const uint32_t* a, uint32_t b0, uint32_t b1) {
    asm volatile(
        "mma.sync.aligned.m16n8k8.row.col.f32.tf32.tf32.f32 "
        "{%0,%1,%2,%3}, {%4,%5,%6,%7}, {%8,%9}, {%0,%1,%2,%3};"
        : "+f"(d[0]), "+f"(d[1]), "+f"(d[2]), "+f"(d[3])
        : "r"(a[0]), "r"(a[1]), "r"(a[2]), "r"(a[3]), "r"(b0), "r"(b1));
}

__global__ void __launch_bounds__(THREADS, 5)
amatch_mma(const float* __restrict__ R, const float* __restrict__ Mx,
           const float* __restrict__ W, float* __restrict__ out)
{
    extern __shared__ char smem[];
    const uint32_t sb = smem_u32(smem);

    const int tid  = threadIdx.x;
    const int lane = tid & 31;
    const int wid  = tid >> 5;     // 0..3 = K quarter
    const int g    = lane >> 2;
    const int t    = lane & 3;
    const int kq   = wid;
    const int row0 = blockIdx.x * ROWS_CTA;

    auto issue_stage = [&](int c, int s) {
        const uint32_t stg = sb + (uint32_t)s * STG_B;
        // A: r and m, 16 rows x 16 float4 = 256 float4 each; 2 per thread per array
#pragma unroll
        for (int i = 0; i < 2; i++) {
            const int idx = i * THREADS + tid;     // 0..255
            const int row = idx >> 4;
            const int k4  = (idx & 15) << 2;
            const size_t go = (size_t)(row0 + row) * D + (size_t)c * KCH + k4;
            const uint32_t so = (uint32_t)(row * SA + k4) * 4u;
            cp16(stg + so,         R  + go);
            cp16(stg + A_ARR + so, Mx + go);
        }
        // B: raw W slice, 24 rows x 16 float4 = 384 float4; rows >= 20 zero-filled
#pragma unroll
        for (int i = 0; i < 3; i++) {
            const int j  = i * THREADS + tid;      // 0..383
            const int n  = j >> 4;
            const int k4 = (j & 15) << 2;
            const int nv = (n < P) ? n : 0;
            const size_t go = (size_t)nv * D + (size_t)c * KCH + k4;
            const uint32_t so = (uint32_t)(2 * A_ARR) + (uint32_t)(n * SA + k4) * 4u;
            cp16p(stg + so, W + go, (n < P) ? 16 : 0);
        }
        cp_commit();
    };

    float acc[3][3][4];   // [type: rm/rr/mm][ntile][cfrag]
#pragma unroll
    for (int a = 0; a < 3; a++)
#pragma unroll
        for (int b = 0; b < 3; b++)
#pragma unroll
            for (int j = 0; j < 4; j++) acc[a][b][j] = 0.f;

    // prologue: stages 0..1
#pragma unroll
    for (int s = 0; s < STAGES - 1; s++) issue_stage(s, s);

    int sidx = 0;   // c % STAGES
    for (int c = 0; c < NCHUNK; ++c) {
        if (c < NCHUNK - 1) cp_wait<1>();
        else                cp_wait<0>();
        __syncthreads();

        if (c + STAGES - 1 < NCHUNK) {
            int s2 = sidx + STAGES - 1;
            if (s2 >= STAGES) s2 -= STAGES;
            issue_stage(c + STAGES - 1, s2);
        }

        const char* stg = smem + sidx * STG_B;
        const float* sr = reinterpret_cast<const float*>(stg);
        const float* sm = reinterpret_cast<const float*>(stg + A_ARR);
        const float* sw = reinterpret_cast<const float*>(stg + 2 * A_ARR);

#pragma unroll
        for (int it = 0; it < 2; it++) {
            const int kl = kq * 16 + it * 8 + t;   // k within chunk

            const int i0 = g * SA + kl;
            const int i1 = i0 + 8 * SA;
            const float r0 = sr[i0], r1 = sr[i1], r2 = sr[i0 + 4], r3 = sr[i1 + 4];
            const float m0 = sm[i0], m1 = sm[i1], m2 = sm[i0 + 4], m3 = sm[i1 + 4];

            uint32_t arm[4] = { f2tf32(r0 * m0), f2tf32(r1 * m1), f2tf32(r2 * m2), f2tf32(r3 * m3) };
            uint32_t arr[4] = { f2tf32(r0 * r0), f2tf32(r1 * r1), f2tf32(r2 * r2), f2tf32(r3 * r3) };
            uint32_t amm[4] = { f2tf32(m0 * m0), f2tf32(m1 * m1), f2tf32(m2 * m2), f2tf32(m3 * m3) };

#pragma unroll
            for (int nt = 0; nt < 3; nt++) {
                const float w0 = sw[(nt * 8 + g) * SA + kl];
                const float w1 = sw[(nt * 8 + g) * SA + kl + 4];
                const uint32_t b0 = f2tf32(w0 * w0);
                const uint32_t b1 = f2tf32(w1 * w1);
                mma8(acc[0][nt], arm, b0, b1);
                mma8(acc[1][nt], arr, b0, b1);
                mma8(acc[2][nt], amm, b0, b1);
            }
        }

        if (++sidx == STAGES) sidx = 0;
    }
    __syncthreads();   // all warps done with stage buffers before aliasing

    // ---- reduce over the 4 K-quarter warps ----
    float* s_red = reinterpret_cast<float*>(smem + OFF_RED);
    if (kq > 0) {
        float* dst = s_red + (size_t)(kq - 1) * 36 * 32 + lane;
#pragma unroll
        for (int a = 0; a < 3; a++)
#pragma unroll
            for (int b = 0; b < 3; b++)
#pragma unroll
                for (int j = 0; j < 4; j++)
                    dst[((a * 3 + b) * 4 + j) * 32] = acc[a][b][j];
    }
    __syncthreads();

    float* s_out = reinterpret_cast<float*>(smem + OFF_OUT);
    if (kq == 0) {
#pragma unroll
        for (int s2 = 0; s2 < 3; s2++) {
            const float* src = s_red + (size_t)s2 * 36 * 32 + lane;
#pragma unroll
            for (int a = 0; a < 3; a++)
#pragma unroll
                for (int b = 0; b < 3; b++)
#pragma unroll
                    for (int j = 0; j < 4; j++)
                        acc[a][b][j] += src[((a * 3 + b) * 4 + j) * 32];
        }
        const float EPS = 1e-8f;
#pragma unroll
        for (int nt = 0; nt < 3; nt++) {
#pragma unroll
            for (int j = 0; j < 4; j++) {
                const int col = nt * 8 + 2 * t + (j & 1);
                const int row = g + (j >> 1) * 8;
                if (col < P) {
                    const float dot = acc[0][nt][j];
                    const float a2  = acc[1][nt][j];
                    const float b2  = acc[2][nt][j];
                    s_out[row * P + col] =
                        dot / (fmaxf(sqrtf(a2), EPS) * fmaxf(sqrtf(b2), EPS));
                }
            }
        }
    }
    __syncthreads();

    // ---- coalesced store: 320 floats = 80 float4 ----
    if (tid < ROWS_CTA * P / 4) {
        float4 v = *reinterpret_cast<float4*>(s_out + tid * 4);
        *reinterpret_cast<float4*>(out + (size_t)row0 * P + tid * 4) = v;
    }
}

extern "C" void kernel_launch(void* const* d_in, const int* in_sizes, int n_in,
                              void* d_out, int out_size)
{
    const float* repres  = (const float*)d_in[0];
    const float* max_att = (const float*)d_in[1];
    const float* weight  = (const float*)d_in[2];
    float* out = (float*)d_out;

    cudaFuncSetAttribute(amatch_mma,
                         cudaFuncAttributeMaxDynamicSharedMemorySize, SMEM_TOTAL);

    amatch_mma<<<NCTA, THREADS, SMEM_TOTAL>>>(repres, max_att, weight, out);
}

// round 11
// speedup vs baseline: 1.1067x; 1.0700x over previous
#include <cuda_runtime.h>
#include <cstdint>

// AtteMatchLay via mma.sync TF32 + 4-deep cp.async pipeline (R7 structure),
// single kernel: B = raw W slices staged per chunk, squared + cvt at read.
//   dot = (r*m) @ w2^T, n1^2 = (r*r) @ w2^T, n2^2 = (m*m) @ w2^T
//   cos = dot / (max(sqrt(n1^2),eps) * max(sqrt(n2^2),eps))
// 256 CTAs x 32 rows, 8 warps = 2 row-strips x 4 K-quarters.
// Per chunk (64 K): cp.async stages r, m ([32][68] padded) and raw W slice
// ([24][68], rows 20..23 zero-filled) -> 23936 B/stage, 4 stages (95744 B).
// R11 fix: B staging loop bound is the ITEM count (NPAD*16 = 384), not
// B_ARR/16 = 408 (padded layout -> bytes/16 != items; i=384..407 produced
// n=24..25 and OOB shared stores on stage 3 -> illegal address).

static constexpr int D        = 768;
static constexpr int P        = 20;
static constexpr int NPAD     = 24;
static constexpr int ROWS_CTA = 32;
static constexpr int THREADS  = 256;
static constexpr int NROWS    = 8192;
static constexpr int NCTA     = NROWS / ROWS_CTA;   // 256
static constexpr int KCH      = 64;
static constexpr int NCHUNK   = D / KCH;            // 12
static constexpr int STAGES   = 4;

static constexpr int SA = 68;                        // row stride (floats), conflict-free
static constexpr int A_ARR   = ROWS_CTA * SA * 4;    // 8704 B per array (r or m)
static constexpr int B_ARR   = NPAD * SA * 4;        // 6528 B (raw W slice [n][k])
static constexpr int B_ITEMS = NPAD * 16;            // 384 float4 of actual data
static constexpr int STG_B   = 2 * A_ARR + B_ARR;    // 23936 B
static constexpr int SMEM_TOTAL = STAGES * STG_B;    // 95744 B -> 2 CTAs/SM

// epilogue aliases (after mainloop + syncthreads)
static constexpr int OFF_RED = 0;       // 2*3*36*32*4 = 27648 B
static constexpr int OFF_OUT = 28672;   // 32*20*4 = 2560 B

__device__ __forceinline__ uint32_t f2tf32(float x) {
    uint32_t t;
    asm("cvt.rna.tf32.f32 %0, %1;" : "=r"(t) : "f"(x));
    return t;
}
__device__ __forceinline__ uint32_t smem_u32(const void* p) {
    uint32_t a;
    asm("{ .reg .u64 t; cvta.to.shared.u64 t, %1; cvt.u32.u64 %0, t; }" : "=r"(a) : "l"(p));
    return a;
}
__device__ __forceinline__ void cp16(uint32_t dst, const void* src) {
    asm volatile("cp.async.cg.shared.global [%0], [%1], 16;" :: "r"(dst), "l"(src));
}
// predicated source: srcbytes=0 -> zero-fill 16 bytes (no global read)
__device__ __forceinline__ void cp16p(uint32_t dst, const void* src, int srcbytes) {
    asm volatile("cp.async.cg.shared.global [%0], [%1], 16, %2;"
                 :: "r"(dst), "l"(src), "r"(srcbytes));
}
__device__ __forceinline__ void cp_commit() {
    asm volatile("cp.async.commit_group;" ::: "memory");
}
template <int N>
__device__ __forceinline__ void cp_wait() {
    asm volatile("cp.async.wait_group %0;" :: "n"(N) : "memory");
}
__device__ __forceinline__ void mma8(float* d, const uint32_t* a, uint32_t b0, uint32_t b1) {
    asm volatile(
        "mma.sync.aligned.m16n8k8.row.col.f32.tf32.tf32.f32 "
        "{%0,%1,%2,%3}, {%4,%5,%6,%7}, {%8,%9}, {%0,%1,%2,%3};"
        : "+f"(d[0]), "+f"(d[1]), "+f"(d[2]), "+f"(d[3])
        : "r"(a[0]), "r"(a[1]), "r"(a[2]), "r"(a[3]), "r"(b0), "r"(b1));
}

__global__ void __launch_bounds__(THREADS, 2)
amatch_mma(const float* __restrict__ R, const float* __restrict__ Mx,
           const float* __restrict__ W, float* __restrict__ out)
{
    extern __shared__ char smem[];
    const uint32_t sb = smem_u32(smem);

    const int tid   = threadIdx.x;
    const int lane  = tid & 31;
    const int wid   = tid >> 5;
    const int g     = lane >> 2;
    const int t     = lane & 3;
    const int strip = wid >> 2;
    const int kq    = wid & 3;
    const int row0  = blockIdx.x * ROWS_CTA;

    // staging thread mapping (A): 512 float4 per array per chunk, 2 per thread
    const int srow0 = tid >> 4;          // rows tid>>4 and tid>>4 + 16
    const int sk4   = (tid & 15) << 2;   // k offset in floats (0,4,...,60)

    auto issue_stage = [&](int c, int s) {
        const uint32_t stg = sb + (uint32_t)s * STG_B;
        const size_t gofs = (size_t)row0 * D + (size_t)c * KCH;
        // A: r and m, 2 rows per thread
#pragma unroll
        for (int i = 0; i < 2; i++) {
            const int row = srow0 + i * 16;
            const size_t go = gofs + (size_t)row * D + sk4;
            const uint32_t so = (uint32_t)(row * SA + sk4) * 4u;
            cp16(stg + so,         R  + go);
            cp16(stg + A_ARR + so, Mx + go);
        }
        // B: raw W slice, 24 rows x 16 float4 = 384 items over 256 threads;
        // rows >= 20 zero-filled (no OOB read)
#pragma unroll
        for (int i = tid; i < B_ITEMS; i += THREADS) {
            const int n  = i >> 4;
            const int k4 = (i & 15) << 2;
            const int nv = (n < P) ? n : 0;
            const size_t go = (size_t)nv * D + (size_t)c * KCH + k4;
            const uint32_t so = (uint32_t)(2 * A_ARR) + (uint32_t)(n * SA + k4) * 4u;
            cp16p(stg + so, W + go, (n < P) ? 16 : 0);
        }
        cp_commit();
    };

    float acc[3][3][4];   // [type: rm/rr/mm][ntile][cfrag]
#pragma unroll
    for (int a = 0; a < 3; a++)
#pragma unroll
        for (int b = 0; b < 3; b++)
#pragma unroll
            for (int j = 0; j < 4; j++) acc[a][b][j] = 0.f;

    // prologue: fill stages 0..2
#pragma unroll
    for (int s = 0; s < STAGES - 1; s++) issue_stage(s, s);

    int sidx = 0;   // c % STAGES
    for (int c = 0; c < NCHUNK; ++c) {
        // chunk c complete when pending groups <= min(2, 11-c)
        if (c <= NCHUNK - 3)      cp_wait<2>();
        else if (c == NCHUNK - 2) cp_wait<1>();
        else                      cp_wait<0>();
        __syncthreads();

        if (c + STAGES - 1 < NCHUNK) {
            int s2 = sidx + STAGES - 1;
            if (s2 >= STAGES) s2 -= STAGES;
            issue_stage(c + STAGES - 1, s2);
        }

        const char* stg = smem + sidx * STG_B;
        const float* sr = reinterpret_cast<const float*>(stg);
        const float* sm = reinterpret_cast<const float*>(stg + A_ARR);
        const float* sw = reinterpret_cast<const float*>(stg + 2 * A_ARR);

#pragma unroll
        for (int it = 0; it < 2; it++) {
            const int kl = kq * 16 + it * 8 + t;   // k within chunk

            const int i0 = (strip * 16 + g) * SA + kl;
            const int i1 = i0 + 8 * SA;
            const float r0 = sr[i0], r1 = sr[i1], r2 = sr[i0 + 4], r3 = sr[i1 + 4];
            const float m0 = sm[i0], m1 = sm[i1], m2 = sm[i0 + 4], m3 = sm[i1 + 4];

            uint32_t arm[4] = { f2tf32(r0 * m0), f2tf32(r1 * m1), f2tf32(r2 * m2), f2tf32(r3 * m3) };
            uint32_t arr[4] = { f2tf32(r0 * r0), f2tf32(r1 * r1), f2tf32(r2 * r2), f2tf32(r3 * r3) };
            uint32_t amm[4] = { f2tf32(m0 * m0), f2tf32(m1 * m1), f2tf32(m2 * m2), f2tf32(m3 * m3) };

#pragma unroll
            for (int nt = 0; nt < 3; nt++) {
                const float w0 = sw[(nt * 8 + g) * SA + kl];
                const float w1 = sw[(nt * 8 + g) * SA + kl + 4];
                const uint32_t b0 = f2tf32(w0 * w0);
                const uint32_t b1 = f2tf32(w1 * w1);
                mma8(acc[0][nt], arm, b0, b1);
                mma8(acc[1][nt], arr, b0, b1);
                mma8(acc[2][nt], amm, b0, b1);
            }
        }

        if (++sidx == STAGES) sidx = 0;
    }
    __syncthreads();   // all warps done with stage buffers before aliasing

    // ---- reduce over the 4 K-quarter warps per strip ----
    float* s_red = reinterpret_cast<float*>(smem + OFF_RED);
    if (kq > 0) {
        float* dst = s_red + (size_t)(strip * 3 + (kq - 1)) * 36 * 32 + lane;
#pragma unroll
        for (int a = 0; a < 3; a++)
#pragma unroll
            for (int b = 0; b < 3; b++)
#pragma unroll
                for (int j = 0; j < 4; j++)
                    dst[((a * 3 + b) * 4 + j) * 32] = acc[a][b][j];
    }
    __syncthreads();

    float* s_out = reinterpret_cast<float*>(smem + OFF_OUT);
    if (kq == 0) {
#pragma unroll
        for (int s2 = 0; s2 < 3; s2++) {
            const float* src = s_red + (size_t)(strip * 3 + s2) * 36 * 32 + lane;
#pragma unroll
            for (int a = 0; a < 3; a++)
#pragma unroll
                for (int b = 0; b < 3; b++)
#pragma unroll
                    for (int j = 0; j < 4; j++)
                        acc[a][b][j] += src[((a * 3 + b) * 4 + j) * 32];
        }
        const float EPS = 1e-8f;
#pragma unroll
        for (int nt = 0; nt < 3; nt++) {
#pragma unroll
            for (int j = 0; j < 4; j++) {
                const int col = nt * 8 + 2 * t + (j & 1);
                const int row = strip * 16 + g + (j >> 1) * 8;
                if (col < P) {
                    const float dot = acc[0][nt][j];
                    const float a2  = acc[1][nt][j];
                    const float b2  = acc[2][nt][j];
                    s_out[row * P + col] =
                        dot / (fmaxf(sqrtf(a2), EPS) * fmaxf(sqrtf(b2), EPS));
                }
            }
        }
    }
    __syncthreads();

    // ---- coalesced store: 640 floats = 160 float4 ----
    if (tid < ROWS_CTA * P / 4) {
        float4 v = *reinterpret_cast<float4*>(s_out + tid * 4);
        *reinterpret_cast<float4*>(out + (size_t)row0 * P + tid * 4) = v;
    }
}

extern "C" void kernel_launch(void* const* d_in, const int* in_sizes, int n_in,
                              void* d_out, int out_size)
{
    const float* repres  = (const float*)d_in[0];
    const float* max_att = (const float*)d_in[1];
    const float* weight  = (const float*)d_in[2];
    float* out = (float*)d_out;

    cudaFuncSetAttribute(amatch_mma,
                         cudaFuncAttributeMaxDynamicSharedMemorySize, SMEM_TOTAL);

    amatch_mma<<<NCTA, THREADS, SMEM_TOTAL>>>(repres, max_att, weight, out);
}